// round 17
// baseline (speedup 1.0000x reference)
#include <cuda_runtime.h>
#include <cuda_fp16.h>
#include <math.h>
#include <float.h>
#include <stdint.h>

#define BATCH 2
#define SEQ   2048
#define DIM   1024
#define NH    16
#define DH    64
#define WIN   512
#define E3    3072
#define MTOT  (BATCH * SEQ)   // 4096
#define KD    1024

// ---------------- scratch (device globals; no allocation) ------------------
__device__ __half g_x16[MTOT * KD];     // x plain fp16
__device__ __half g_wq[KD * E3];        // Wqkv fp16 [K][N] (row-major, no transpose)
__device__ __half g_wo[KD * DIM];       // Wout fp16 [K][N]
__device__ __half g_qkv[MTOT * E3];     // qkv plain fp16 (Q pre-scaled)
__device__ __half g_c16[MTOT * KD];     // ctx plain fp16

// ---------------- helpers ---------------------------------------------------
__device__ __forceinline__ uint32_t pack_f16(float x, float y) {
    __half2 h = __floats2half2_rn(x, y);
    return *(uint32_t*)&h;
}
__device__ __forceinline__ void mma_f16(float* c, const uint32_t* a, const uint32_t* b) {
    asm volatile(
        "mma.sync.aligned.m16n8k16.row.col.f32.f16.f16.f32 "
        "{%0,%1,%2,%3}, {%4,%5,%6,%7}, {%8,%9}, {%0,%1,%2,%3};"
        : "+f"(c[0]), "+f"(c[1]), "+f"(c[2]), "+f"(c[3])
        : "r"(a[0]), "r"(a[1]), "r"(a[2]), "r"(a[3]), "r"(b[0]), "r"(b[1]));
}
__device__ __forceinline__ uint32_t smem_u32(const void* p) {
    return (uint32_t)__cvta_generic_to_shared(p);
}
#define CP16(s, g) \
    asm volatile("cp.async.cg.shared.global [%0], [%1], 16;" :: "r"(s), "l"(g))
#define CP_COMMIT() asm volatile("cp.async.commit_group;")
#define CP_WAIT(n)  asm volatile("cp.async.wait_group %0;" :: "n"(n))
#define LDSM4(r, a) \
    asm volatile("ldmatrix.sync.aligned.m8n8.x4.shared.b16 {%0,%1,%2,%3}, [%4];" \
        : "=r"((r)[0]), "=r"((r)[1]), "=r"((r)[2]), "=r"((r)[3]) : "r"(a))
#define LDSM4T(r, a) \
    asm volatile("ldmatrix.sync.aligned.m8n8.x4.trans.shared.b16 {%0,%1,%2,%3}, [%4];" \
        : "=r"((r)[0]), "=r"((r)[1]), "=r"((r)[2]), "=r"((r)[3]) : "r"(a))

// ---------------------------------------------------------------------------
// Prep: generic fp32 -> fp16 elementwise convert (4 elems / thread)
// ---------------------------------------------------------------------------
__global__ __launch_bounds__(256) void convert_kernel(
    const float* __restrict__ src, __half* __restrict__ dst)
{
    int i = blockIdx.x * 256 + threadIdx.x;
    float4 v = ((const float4*)src)[i];
    ((uint2*)dst)[i] = make_uint2(pack_f16(v.x, v.y), pack_f16(v.z, v.w));
}

// ---------------------------------------------------------------------------
// fp16 single-pass GEMM: C = A*B, f32 acc.
// A: [M][K] fp16 K-major. B: [K][N] fp16 row-major (ldmatrix.trans fragments).
// Block tile 128x128, BK=64, 256 thr = 8 warps (2m x 4n of 64x32), 2 CTA/SM.
// MODE 0: fp32 C.  MODE 1: plain fp16 C, cols < qcols scaled by 0.125 (Q).
// ---------------------------------------------------------------------------
#define LDTA     72                           // A fp16 row stride (64 + 8 pad)
#define LDTB     136                          // B fp16 row stride (128 + 8 pad)
#define A_BYTES  (128 * LDTA * 2)             // 18432
#define B_BYTES  (64 * LDTB * 2)              // 17408
#define STG      (A_BYTES + B_BYTES)          // 35840
#define GEMM_SMEM (2 * STG)                   // 71680

template <int MODE>
__global__ __launch_bounds__(256, 2) void gemm_1p(
    const __half* __restrict__ Ap, const __half* __restrict__ Bp,
    float* __restrict__ Cf, __half* __restrict__ Ch,
    int M, int N, int K, int qcols)
{
    extern __shared__ char smem[];
    const uint32_t sb = smem_u32(smem);
    const int tid = threadIdx.x, wid = tid >> 5, lane = tid & 31;
    const int wm = (wid & 1) * 64, wn = (wid >> 1) * 32;
    const long arow0 = (long)blockIdx.y * 128;
    const int  bn0   = blockIdx.x * 128;

    float acc[4][4][4] = {};

    const uint32_t a_off =
        (uint32_t)((wm + (lane & 7) + ((lane & 8) ? 8 : 0)) * (LDTA * 2)
                   + ((lane & 16) ? 16 : 0));
    // B (trans): row = k = (lane&7) + ((lane&8)?8:0); col = wn + ((lane&16)?8:0) n
    const uint32_t b_off = (uint32_t)(A_BYTES
                   + ((lane & 7) + ((lane & 8) ? 8 : 0)) * (LDTB * 2)
                   + wn * 2 + ((lane & 16) ? 16 : 0));

    const int nT = K / 64;

    auto issue = [&](int t) {
        const int s = t & 1, k0 = t * 64;
        const uint32_t st = sb + s * STG;
        // A: 1024 chunks (128 rows x 8 chunks of 16B)
#pragma unroll
        for (int i = 0; i < 4; i++) {
            int idx = i * 256 + tid;
            int row = idx >> 3, kc = idx & 7;
            CP16(st + row * (LDTA * 2) + kc * 16,
                 Ap + (arow0 + row) * K + k0 + kc * 8);
        }
        // B: 1024 chunks (64 k-rows x 16 chunks of 8 n)
#pragma unroll
        for (int i = 0; i < 4; i++) {
            int idx = i * 256 + tid;
            int row = idx >> 4, nc = idx & 15;
            CP16(st + A_BYTES + row * (LDTB * 2) + nc * 16,
                 Bp + (long)(k0 + row) * N + bn0 + nc * 8);
        }
        CP_COMMIT();
    };

    issue(0);
    for (int t = 0; t < nT; t++) {
        if (t + 1 < nT) { issue(t + 1); CP_WAIT(1); }
        else            { CP_WAIT(0); }
        __syncthreads();

        const uint32_t st = sb + (t & 1) * STG;
#pragma unroll
        for (int ks = 0; ks < 4; ks++) {
            uint32_t ah[4][4], bh[4][2];
#pragma unroll
            for (int am = 0; am < 4; am++)
                LDSM4(ah[am], st + a_off + am * (16 * LDTA * 2) + ks * 32);
#pragma unroll
            for (int g = 0; g < 2; g++) {
                uint32_t a = st + b_off + ks * (16 * LDTB * 2) + g * 32;
                uint32_t r[4];
                LDSM4T(r, a);
                bh[2*g][0] = r[0]; bh[2*g][1] = r[1];
                bh[2*g+1][0] = r[2]; bh[2*g+1][1] = r[3];
            }
#pragma unroll
            for (int am = 0; am < 4; am++)
#pragma unroll
                for (int bn = 0; bn < 4; bn++)
                    mma_f16(acc[am][bn], ah[am], bh[bn]);
        }
        __syncthreads();
    }

    // epilogue
#pragma unroll
    for (int am = 0; am < 4; am++)
#pragma unroll
        for (int bn = 0; bn < 4; bn++) {
            int row = blockIdx.y * 128 + wm + am * 16 + (lane >> 2);
            int col = bn0 + wn + bn * 8 + 2 * (lane & 3);
            if (MODE == 0) {
                *(float2*)(Cf + (long)row * N + col) =
                    make_float2(acc[am][bn][0], acc[am][bn][1]);
                *(float2*)(Cf + (long)(row + 8) * N + col) =
                    make_float2(acc[am][bn][2], acc[am][bn][3]);
            } else {
                float scl = (col < qcols) ? 0.125f : 1.0f;
                *(uint32_t*)(Ch + (long)row * N + col) =
                    pack_f16(acc[am][bn][0] * scl, acc[am][bn][1] * scl);
                *(uint32_t*)(Ch + (long)(row + 8) * N + col) =
                    pack_f16(acc[am][bn][2] * scl, acc[am][bn][3] * scl);
            }
        }
}

// ---------------------------------------------------------------------------
// Sliding-window flash attention, all-plain fp16 single-pass, with
// warp-uniform skipping of fully-masked mma blocks.
//   S = Q * K^T ; O = P * V. 128 q-rows/block, 4 warps, key tile 64.
// ---------------------------------------------------------------------------
#define KVP 72   // fp16 per smem row (64 + 8 pad)

__global__ __launch_bounds__(128) void attn_mma(
    const __half* __restrict__ qkv, __half* __restrict__ ctx16)
{
    __shared__ __half Ks[64 * KVP];
    __shared__ __half Vs[64 * KVP];

    const int tid  = threadIdx.x;
    const int wid  = tid >> 5;
    const int lane = tid & 31;
    const int gid  = lane >> 2;
    const int tig  = lane & 3;
    const int i0   = blockIdx.x * 128;
    const int h    = blockIdx.y;
    const int b    = blockIdx.z;

    const long rowb = (long)b * SEQ;
    const int qcol = h * DH;
    const int kcol = DIM + h * DH;
    const int vcol = 2 * DIM + h * DH;

    const int qi_lo = i0 + wid * 32;       // warp's q-row range
    const int qi_hi = qi_lo + 31;

    uint32_t qf[2][4][4];
#pragma unroll
    for (int am = 0; am < 2; am++) {
        long r = rowb + i0 + wid * 32 + am * 16 + gid;
#pragma unroll
        for (int s = 0; s < 4; s++) {
            int c = qcol + s * 16 + 2 * tig;
            qf[am][s][0] = *(const uint32_t*)(qkv + r * E3 + c);
            qf[am][s][1] = *(const uint32_t*)(qkv + (r + 8) * E3 + c);
            qf[am][s][2] = *(const uint32_t*)(qkv + r * E3 + c + 8);
            qf[am][s][3] = *(const uint32_t*)(qkv + (r + 8) * E3 + c + 8);
        }
    }

    const uint32_t ks_b = smem_u32(Ks), vs_b = smem_u32(Vs);
    const uint32_t koff = (uint32_t)(((lane & 7) + ((lane & 16) ? 8 : 0)) * (KVP * 2)
                                     + ((lane & 8) ? 16 : 0));
    const uint32_t voff = (uint32_t)(((lane & 7) + ((lane & 8) ? 8 : 0)) * (KVP * 2)
                                     + ((lane & 16) ? 16 : 0));

    float mrow[2][2], lrow[2][2], o[2][8][4] = {};
#pragma unroll
    for (int am = 0; am < 2; am++) {
        mrow[am][0] = -FLT_MAX; mrow[am][1] = -FLT_MAX;
        lrow[am][0] = 0.f;      lrow[am][1] = 0.f;
    }

    int t0 = (i0 - WIN + 1) >> 6; if (t0 < 0) t0 = 0;
    const int t1 = (i0 + 127) >> 6;

    for (int t = t0; t <= t1; t++) {
        const int kt0 = t << 6;
        __syncthreads();

#pragma unroll
        for (int i = 0; i < 4; i++) {
            int idx = i * 128 + tid;
            int row = idx >> 3, ch = idx & 7;
            long gro = (rowb + kt0 + row) * E3;
            uint32_t so = row * (KVP * 2) + ch * 16;
            CP16(ks_b + so, qkv + gro + kcol + ch * 8);
            CP16(vs_b + so, qkv + gro + vcol + ch * 8);
        }
        CP_COMMIT();
        CP_WAIT(0);
        __syncthreads();

        // ---- S = Q K^T  (skip fully-masked 8-key blocks; warp-uniform)
        float s[2][8][4] = {};
#pragma unroll
        for (int ks = 0; ks < 4; ks++) {
            uint32_t kf[8][2];
#pragma unroll
            for (int g = 0; g < 4; g++) {
                int kgl = kt0 + g * 16;
                if (kgl > qi_hi || kgl + 15 < qi_lo - (WIN - 1)) continue;
                uint32_t a = koff + g * (16 * KVP * 2) + ks * 32;
                uint32_t r[4];
                LDSM4(r, ks_b + a);
                kf[2*g][0] = r[0]; kf[2*g][1] = r[1];
                kf[2*g+1][0] = r[2]; kf[2*g+1][1] = r[3];
            }
#pragma unroll
            for (int bn = 0; bn < 8; bn++) {
                int c_lo = kt0 + bn * 8;
                if (c_lo > qi_hi || c_lo + 7 < qi_lo - (WIN - 1)) continue;
#pragma unroll
                for (int am = 0; am < 2; am++)
                    mma_f16(s[am][bn], qf[am][ks], kf[bn]);
            }
        }

        // ---- mask + online softmax
#pragma unroll
        for (int am = 0; am < 2; am++) {
            int qi0 = i0 + wid * 32 + am * 16 + gid;
            int qi1 = qi0 + 8;
#pragma unroll
            for (int bn = 0; bn < 8; bn++) {
                int c0 = kt0 + bn * 8 + 2 * tig, c1 = c0 + 1;
                if (c0 > qi0 || c0 < qi0 - (WIN - 1)) s[am][bn][0] = -FLT_MAX;
                if (c1 > qi0 || c1 < qi0 - (WIN - 1)) s[am][bn][1] = -FLT_MAX;
                if (c0 > qi1 || c0 < qi1 - (WIN - 1)) s[am][bn][2] = -FLT_MAX;
                if (c1 > qi1 || c1 < qi1 - (WIN - 1)) s[am][bn][3] = -FLT_MAX;
            }
            float mx0 = -FLT_MAX, mx1 = -FLT_MAX;
#pragma unroll
            for (int bn = 0; bn < 8; bn++) {
                mx0 = fmaxf(mx0, fmaxf(s[am][bn][0], s[am][bn][1]));
                mx1 = fmaxf(mx1, fmaxf(s[am][bn][2], s[am][bn][3]));
            }
            mx0 = fmaxf(mx0, __shfl_xor_sync(0xffffffffu, mx0, 1));
            mx0 = fmaxf(mx0, __shfl_xor_sync(0xffffffffu, mx0, 2));
            mx1 = fmaxf(mx1, __shfl_xor_sync(0xffffffffu, mx1, 1));
            mx1 = fmaxf(mx1, __shfl_xor_sync(0xffffffffu, mx1, 2));
            float mn0 = fmaxf(mrow[am][0], mx0);
            float mn1 = fmaxf(mrow[am][1], mx1);
            float a0 = __expf(mrow[am][0] - mn0);
            float a1 = __expf(mrow[am][1] - mn1);
            mrow[am][0] = mn0; mrow[am][1] = mn1;
            float rs0 = 0.f, rs1 = 0.f;
#pragma unroll
            for (int bn = 0; bn < 8; bn++) {
                s[am][bn][0] = __expf(s[am][bn][0] - mn0);
                s[am][bn][1] = __expf(s[am][bn][1] - mn0);
                s[am][bn][2] = __expf(s[am][bn][2] - mn1);
                s[am][bn][3] = __expf(s[am][bn][3] - mn1);
                rs0 += s[am][bn][0] + s[am][bn][1];
                rs1 += s[am][bn][2] + s[am][bn][3];
            }
            rs0 += __shfl_xor_sync(0xffffffffu, rs0, 1);
            rs0 += __shfl_xor_sync(0xffffffffu, rs0, 2);
            rs1 += __shfl_xor_sync(0xffffffffu, rs1, 1);
            rs1 += __shfl_xor_sync(0xffffffffu, rs1, 2);
            lrow[am][0] = lrow[am][0] * a0 + rs0;
            lrow[am][1] = lrow[am][1] * a1 + rs1;
#pragma unroll
            for (int bn = 0; bn < 8; bn++) {
                o[am][bn][0] *= a0; o[am][bn][1] *= a0;
                o[am][bn][2] *= a1; o[am][bn][3] *= a1;
            }
        }

        // ---- P fragments (plain fp16) from S accumulators
        uint32_t pf[2][4][4];
#pragma unroll
        for (int am = 0; am < 2; am++)
#pragma unroll
            for (int kk = 0; kk < 4; kk++) {
                pf[am][kk][0] = pack_f16(s[am][2*kk][0],   s[am][2*kk][1]);
                pf[am][kk][1] = pack_f16(s[am][2*kk][2],   s[am][2*kk][3]);
                pf[am][kk][2] = pack_f16(s[am][2*kk+1][0], s[am][2*kk+1][1]);
                pf[am][kk][3] = pack_f16(s[am][2*kk+1][2], s[am][2*kk+1][3]);
            }

        // ---- O += P V  (skip fully-masked 16-key chunks; warp-uniform)
#pragma unroll
        for (int kk = 0; kk < 4; kk++) {
            int k_lo = kt0 + kk * 16;
            if (k_lo > qi_hi || k_lo + 15 < qi_lo - (WIN - 1)) continue;
            uint32_t vf[8][2];
#pragma unroll
            for (int g = 0; g < 4; g++) {
                uint32_t a = voff + kk * (16 * KVP * 2) + g * 32;
                uint32_t r[4];
                LDSM4T(r, vs_b + a);
                vf[2*g][0] = r[0]; vf[2*g][1] = r[1];
                vf[2*g+1][0] = r[2]; vf[2*g+1][1] = r[3];
            }
#pragma unroll
            for (int bn = 0; bn < 8; bn++)
#pragma unroll
                for (int am = 0; am < 2; am++)
                    mma_f16(o[am][bn], pf[am][kk], vf[bn]);
        }
    }

    // ---- epilogue: normalize, plain fp16 ctx
#pragma unroll
    for (int am = 0; am < 2; am++) {
        float inv0 = 1.f / lrow[am][0];
        float inv1 = 1.f / lrow[am][1];
        long r0 = rowb + i0 + wid * 32 + am * 16 + gid;
#pragma unroll
        for (int bn = 0; bn < 8; bn++) {
            int col = h * DH + bn * 8 + 2 * tig;
            *(uint32_t*)(ctx16 + r0 * DIM + col) =
                pack_f16(o[am][bn][0] * inv0, o[am][bn][1] * inv0);
            *(uint32_t*)(ctx16 + (r0 + 8) * DIM + col) =
                pack_f16(o[am][bn][2] * inv1, o[am][bn][3] * inv1);
        }
    }
}

// ---------------------------------------------------------------------------
extern "C" void kernel_launch(void* const* d_in, const int* in_sizes, int n_in,
                              void* d_out, int out_size)
{
    (void)in_sizes; (void)n_in; (void)out_size;
    const float* x    = (const float*)d_in[0];
    const float* Wqkv = (const float*)d_in[1];
    const float* Wout = (const float*)d_in[2];
    float* out = (float*)d_out;

    __half *x16, *wq, *wo, *qkv, *c16;
    cudaGetSymbolAddress((void**)&x16, g_x16);
    cudaGetSymbolAddress((void**)&wq,  g_wq);
    cudaGetSymbolAddress((void**)&wo,  g_wo);
    cudaGetSymbolAddress((void**)&qkv, g_qkv);
    cudaGetSymbolAddress((void**)&c16, g_c16);

    cudaFuncSetAttribute(gemm_1p<0>,
                         cudaFuncAttributeMaxDynamicSharedMemorySize, GEMM_SMEM);
    cudaFuncSetAttribute(gemm_1p<1>,
                         cudaFuncAttributeMaxDynamicSharedMemorySize, GEMM_SMEM);

    // prep: pure elementwise fp32 -> fp16 converts (no transposes)
    convert_kernel<<<(MTOT * KD) / 1024, 256>>>(x, x16);
    convert_kernel<<<(KD * E3) / 1024, 256>>>(Wqkv, wq);
    convert_kernel<<<(KD * DIM) / 1024, 256>>>(Wout, wo);

    // 1) QKV projection (single pass, BK=64) -> plain fp16 qkv (Q pre-scaled)
    gemm_1p<1><<<dim3(E3 / 128, MTOT / 128), 256, GEMM_SMEM>>>(
        x16, wq, nullptr, qkv, MTOT, E3, KD, DIM);

    // 2) sliding-window attention (single pass, mask-skip) -> plain fp16 ctx
    attn_mma<<<dim3(SEQ / 128, NH, BATCH), 128>>>(qkv, c16);

    // 3) output projection (single pass, BK=64) -> fp32 out
    gemm_1p<0><<<dim3(DIM / 128, MTOT / 128), 256, GEMM_SMEM>>>(
        c16, wo, out, nullptr, MTOT, DIM, KD, 0);
}